// round 12
// baseline (speedup 1.0000x reference)
#include <cuda_runtime.h>
#include <cuda_fp16.h>
#include <math.h>

#define NN 100000          // nodes
#define NE 3200000         // edges
#define NG 512             // graphs
#define NF 128             // input features
#define BN_EPS 1e-5f
#define STR1 (NN * 32)     // stride of one agg1 fp16 buffer

// ---------------- scratch (device globals; no allocations allowed) ----------
__device__ __half g_y1h[NN * 32];       // fp16(x @ W_rel1), padded 30->32 (64B rows)
__device__ __half g_agg1h[4 * STR1];    // 4-way split fp16 accumulators (edge e -> buf e&3)
__device__ float  g_y2[NN * 20];        // h @ W_rel2' (bn1 folded)
__device__ float  g_agg2[NN * 20];      // init = h @ W_root2' + b2'; fp32 RED adds edges

// ---------------- helpers ----------------------------------------------------
__device__ __forceinline__ void red_add_v4_f32(float* p, float4 v) {
    asm volatile("red.global.add.v4.f32 [%0], {%1, %2, %3, %4};"
                 :: "l"(__cvta_generic_to_global(p)),
                    "f"(v.x), "f"(v.y), "f"(v.z), "f"(v.w)
                 : "memory");
}

__device__ __forceinline__ void red_add_v4_f16x2(__half* p, uint4 v) {
    asm volatile("red.global.add.noftz.v4.f16x2 [%0], {%1, %2, %3, %4};"
                 :: "l"(__cvta_generic_to_global(p)),
                    "r"(v.x), "r"(v.y), "r"(v.z), "r"(v.w)
                 : "memory");
}

__device__ __forceinline__ float2 ffma2(float2 a, float2 b, float2 c) {
    float2 d;
    asm("fma.rn.f32x2 %0, %1, %2, %3;"
        : "=l"(reinterpret_cast<unsigned long long&>(d))
        : "l"(reinterpret_cast<unsigned long long&>(a)),
          "l"(reinterpret_cast<unsigned long long&>(b)),
          "l"(reinterpret_cast<unsigned long long&>(c)));
    return d;
}

// ---------------- kernel 1: node transform 1 (2 nodes/thread) ----------------
// per node: g_y1h = fp16(x @ W_rel1); agg1 buf0 = fp16(x @ W_root1 + b1); bufs 1-3 = 0
__global__ void __launch_bounds__(128) k_node1(
    const float* __restrict__ x,
    const float* __restrict__ Wrel,   // [128,30]
    const float* __restrict__ Wroot,  // [128,30]
    const float* __restrict__ b1,     // [30]
    int n)
{
    __shared__ float Ws[128 * 60];    // row k: [rel 30 | root 30]
    __shared__ float bs[30];
    for (int i = threadIdx.x; i < 128 * 30; i += 128) {
        int k = i / 30, j = i % 30;
        Ws[k * 60 + j]      = Wrel[i];
        Ws[k * 60 + 30 + j] = Wroot[i];
    }
    if (threadIdx.x < 30) bs[threadIdx.x] = b1[threadIdx.x];
    __syncthreads();

    int nodeA = blockIdx.x * 256 + threadIdx.x;
    int nodeB = nodeA + 128;
    int rA = min(nodeA, n - 1);
    int rB = min(nodeB, n - 1);

    float2 a0[30], a1[30];            // pairs: 0..14 rel, 15..29 root
#pragma unroll
    for (int p = 0; p < 30; p++) { a0[p] = make_float2(0.f, 0.f); a1[p] = make_float2(0.f, 0.f); }

    const float4* xrA = reinterpret_cast<const float4*>(x) + rA * 32;
    const float4* xrB = reinterpret_cast<const float4*>(x) + rB * 32;
#pragma unroll 2
    for (int k4 = 0; k4 < 32; k4++) {
        float4 xA = __ldg(xrA + k4);
        float4 xB = __ldg(xrB + k4);
#pragma unroll
        for (int q = 0; q < 4; q++) {
            float sA = (q == 0) ? xA.x : (q == 1) ? xA.y : (q == 2) ? xA.z : xA.w;
            float sB = (q == 0) ? xB.x : (q == 1) ? xB.y : (q == 2) ? xB.z : xB.w;
            float2 bA = make_float2(sA, sA);
            float2 bB = make_float2(sB, sB);
            const float4* w4 = reinterpret_cast<const float4*>(&Ws[(k4 * 4 + q) * 60]);
#pragma unroll
            for (int j4 = 0; j4 < 15; j4++) {
                float4 wv = w4[j4];
                float2 wlo = make_float2(wv.x, wv.y);
                float2 whi = make_float2(wv.z, wv.w);
                a0[j4 * 2]     = ffma2(wlo, bA, a0[j4 * 2]);
                a0[j4 * 2 + 1] = ffma2(whi, bA, a0[j4 * 2 + 1]);
                a1[j4 * 2]     = ffma2(wlo, bB, a1[j4 * 2]);
                a1[j4 * 2 + 1] = ffma2(whi, bB, a1[j4 * 2 + 1]);
            }
        }
    }

    uint4 z4 = make_uint4(0u, 0u, 0u, 0u);
    if (nodeA < n) {
        __half2 h2[16];
#pragma unroll
        for (int p = 0; p < 15; p++) h2[p] = __float22half2_rn(a0[p]);
        h2[15] = __float2half2_rn(0.f);
        uint4* yo = reinterpret_cast<uint4*>(g_y1h + nodeA * 32);
#pragma unroll
        for (int c = 0; c < 4; c++) yo[c] = reinterpret_cast<uint4*>(h2)[c];

        __half2 g2[16];
#pragma unroll
        for (int p = 0; p < 15; p++)
            g2[p] = __float22half2_rn(make_float2(a0[15 + p].x + bs[2 * p],
                                                  a0[15 + p].y + bs[2 * p + 1]));
        g2[15] = __float2half2_rn(0.f);
        uint4* ao = reinterpret_cast<uint4*>(g_agg1h + nodeA * 32);
#pragma unroll
        for (int c = 0; c < 4; c++) ao[c] = reinterpret_cast<uint4*>(g2)[c];
#pragma unroll
        for (int b = 1; b < 4; b++) {
            uint4* zo = reinterpret_cast<uint4*>(g_agg1h + (size_t)b * STR1 + nodeA * 32);
#pragma unroll
            for (int c = 0; c < 4; c++) zo[c] = z4;
        }
    }
    if (nodeB < n) {
        __half2 h2[16];
#pragma unroll
        for (int p = 0; p < 15; p++) h2[p] = __float22half2_rn(a1[p]);
        h2[15] = __float2half2_rn(0.f);
        uint4* yo = reinterpret_cast<uint4*>(g_y1h + nodeB * 32);
#pragma unroll
        for (int c = 0; c < 4; c++) yo[c] = reinterpret_cast<uint4*>(h2)[c];

        __half2 g2[16];
#pragma unroll
        for (int p = 0; p < 15; p++)
            g2[p] = __float22half2_rn(make_float2(a1[15 + p].x + bs[2 * p],
                                                  a1[15 + p].y + bs[2 * p + 1]));
        g2[15] = __float2half2_rn(0.f);
        uint4* ao = reinterpret_cast<uint4*>(g_agg1h + nodeB * 32);
#pragma unroll
        for (int c = 0; c < 4; c++) ao[c] = reinterpret_cast<uint4*>(g2)[c];
#pragma unroll
        for (int b = 1; b < 4; b++) {
            uint4* zo = reinterpret_cast<uint4*>(g_agg1h + (size_t)b * STR1 + nodeB * 32);
#pragma unroll
            for (int c = 0; c < 4; c++) zo[c] = z4;
        }
    }
}

// ---------------- kernel 2: edge scatter 1 (4 chunk-lanes/edge, fp16 RED) ----
// edge e accumulates into split buffer (e & 3)
__global__ void __launch_bounds__(256) k_scatter1(const int* __restrict__ ei, int nE)
{
    long long gtid = (long long)blockIdx.x * blockDim.x + threadIdx.x;
    if (gtid >= (long long)nE * 4) return;
    int e = (int)(gtid >> 2);
    int c = (int)(gtid & 3);
    int s = __ldg(&ei[e]);
    int d = __ldg(&ei[nE + e]);
    uint4 v = __ldg(reinterpret_cast<const uint4*>(g_y1h) + s * 4 + c);
    int buf = e & 3;
    red_add_v4_f16x2(g_agg1h + (size_t)buf * STR1 + d * 32 + c * 8, v);
}

// ---------------- kernel 3: node transform 2 (2 nodes/thread, bn1 folded) ---
__global__ void __launch_bounds__(128) k_node2(
    const float* __restrict__ bn1_g, const float* __restrict__ bn1_b,
    const float* __restrict__ bn1_m, const float* __restrict__ bn1_v,
    const float* __restrict__ Wrel2,   // [30,20]
    const float* __restrict__ Wroot2,  // [30,20]
    const float* __restrict__ b2,      // [20]
    int n)
{
    __shared__ float Ws[30 * 40];     // row k: [rel 20 | root 20] scaled by sc1[k]
    __shared__ float sc1[30], sh1[30];
    __shared__ float cr[20], cq[20];

    if (threadIdx.x < 30) {
        float sc = bn1_g[threadIdx.x] * rsqrtf(bn1_v[threadIdx.x] + BN_EPS);
        sc1[threadIdx.x] = sc;
        sh1[threadIdx.x] = bn1_b[threadIdx.x] - bn1_m[threadIdx.x] * sc;
    }
    __syncthreads();
    for (int i = threadIdx.x; i < 30 * 20; i += 128) {
        int k = i / 20, j = i % 20;
        Ws[k * 40 + j]      = sc1[k] * Wrel2[i];
        Ws[k * 40 + 20 + j] = sc1[k] * Wroot2[i];
    }
    if (threadIdx.x < 40) {
        int j = threadIdx.x % 20;
        float s = (threadIdx.x < 20) ? 0.f : b2[j];
        if (threadIdx.x < 20) {
            for (int k = 0; k < 30; k++) s += sh1[k] * Wrel2[k * 20 + j];
            cr[j] = s;
        } else {
            for (int k = 0; k < 30; k++) s += sh1[k] * Wroot2[k * 20 + j];
            cq[j] = s;
        }
    }
    __syncthreads();

    int nodeA = blockIdx.x * 256 + threadIdx.x;
    int nodeB = nodeA + 128;
    int rA = min(nodeA, n - 1);
    int rB = min(nodeB, n - 1);

    // sum 4 split fp16 buffers in fp32, then relu
    float hA[30], hB[30];
    {
        float2 accA[15], accB[15];
#pragma unroll
        for (int p = 0; p < 15; p++) { accA[p] = make_float2(0.f, 0.f); accB[p] = make_float2(0.f, 0.f); }
#pragma unroll
        for (int b = 0; b < 4; b++) {
            const uint4* arA = reinterpret_cast<const uint4*>(g_agg1h + (size_t)b * STR1 + rA * 32);
            const uint4* arB = reinterpret_cast<const uint4*>(g_agg1h + (size_t)b * STR1 + rB * 32);
            uint4 qA[4], qB[4];
#pragma unroll
            for (int c = 0; c < 4; c++) { qA[c] = __ldg(arA + c); qB[c] = __ldg(arB + c); }
            const __half2* hpA = reinterpret_cast<const __half2*>(qA);
            const __half2* hpB = reinterpret_cast<const __half2*>(qB);
#pragma unroll
            for (int p = 0; p < 15; p++) {
                float2 fA = __half22float2(hpA[p]);
                float2 fB = __half22float2(hpB[p]);
                accA[p].x += fA.x; accA[p].y += fA.y;
                accB[p].x += fB.x; accB[p].y += fB.y;
            }
        }
#pragma unroll
        for (int p = 0; p < 15; p++) {
            hA[2 * p]     = fmaxf(accA[p].x, 0.f);
            hA[2 * p + 1] = fmaxf(accA[p].y, 0.f);
            hB[2 * p]     = fmaxf(accB[p].x, 0.f);
            hB[2 * p + 1] = fmaxf(accB[p].y, 0.f);
        }
    }

    float2 acA[20], acB[20];          // pairs: 0..9 rel, 10..19 root
#pragma unroll
    for (int p = 0; p < 10; p++) {
        acA[p]      = make_float2(cr[p*2], cr[p*2+1]);
        acA[10 + p] = make_float2(cq[p*2], cq[p*2+1]);
        acB[p]      = acA[p];
        acB[10 + p] = acA[10 + p];
    }

#pragma unroll
    for (int k = 0; k < 30; k++) {
        float2 bA = make_float2(hA[k], hA[k]);
        float2 bB = make_float2(hB[k], hB[k]);
        const float4* w4 = reinterpret_cast<const float4*>(&Ws[k * 40]);
#pragma unroll
        for (int j4 = 0; j4 < 10; j4++) {
            float4 wv = w4[j4];
            float2 wlo = make_float2(wv.x, wv.y);
            float2 whi = make_float2(wv.z, wv.w);
            acA[j4 * 2]     = ffma2(wlo, bA, acA[j4 * 2]);
            acA[j4 * 2 + 1] = ffma2(whi, bA, acA[j4 * 2 + 1]);
            acB[j4 * 2]     = ffma2(wlo, bB, acB[j4 * 2]);
            acB[j4 * 2 + 1] = ffma2(whi, bB, acB[j4 * 2 + 1]);
        }
    }

    if (nodeA < n) {
        float4* y = reinterpret_cast<float4*>(g_y2 + nodeA * 20);
        float4* a = reinterpret_cast<float4*>(g_agg2 + nodeA * 20);
#pragma unroll
        for (int j4 = 0; j4 < 5; j4++) {
            y[j4] = make_float4(acA[j4*2].x, acA[j4*2].y, acA[j4*2+1].x, acA[j4*2+1].y);
            a[j4] = make_float4(acA[10+j4*2].x, acA[10+j4*2].y, acA[11+j4*2].x, acA[11+j4*2].y);
        }
    }
    if (nodeB < n) {
        float4* y = reinterpret_cast<float4*>(g_y2 + nodeB * 20);
        float4* a = reinterpret_cast<float4*>(g_agg2 + nodeB * 20);
#pragma unroll
        for (int j4 = 0; j4 < 5; j4++) {
            y[j4] = make_float4(acB[j4*2].x, acB[j4*2].y, acB[j4*2+1].x, acB[j4*2+1].y);
            a[j4] = make_float4(acB[10+j4*2].x, acB[10+j4*2].y, acB[11+j4*2].x, acB[11+j4*2].y);
        }
    }
}

// ---------------- kernel 4: edge scatter 2 (5 chunk-lanes/edge, fp32 RED) ----
__global__ void __launch_bounds__(256) k_scatter2(const int* __restrict__ ei, int nE)
{
    long long gtid = (long long)blockIdx.x * blockDim.x + threadIdx.x;
    if (gtid >= (long long)nE * 5) return;
    unsigned int u = (unsigned int)gtid;
    unsigned int e = u / 5u;
    unsigned int c = u - e * 5u;
    int s = __ldg(&ei[e]);
    int d = __ldg(&ei[nE + e]);
    float4 v = __ldg(reinterpret_cast<const float4*>(g_y2) + s * 5 + c);
    red_add_v4_f32(g_agg2 + d * 20 + c * 4, v);
}

// ---------------- kernel 5: per-graph pooling + MLP head ---------------------
__global__ void __launch_bounds__(32) k_pool_head(
    const int* __restrict__ batch, int n,
    const float* __restrict__ bn2_g, const float* __restrict__ bn2_b,
    const float* __restrict__ bn2_m, const float* __restrict__ bn2_v,
    const float* __restrict__ W1,    // [40,10]
    const float* __restrict__ bl1,   // [10]
    const float* __restrict__ W2,    // [10,1]
    const float* __restrict__ bl2,   // [1]
    float* __restrict__ out)
{
    int g = blockIdx.x;
    int lane = threadIdx.x;

    int lo = 0, hi = n;
    while (lo < hi) { int mid = (lo + hi) >> 1; if (__ldg(&batch[mid]) < g) lo = mid + 1; else hi = mid; }
    int start = lo;
    lo = start; hi = n;
    while (lo < hi) { int mid = (lo + hi) >> 1; if (__ldg(&batch[mid]) < g + 1) lo = mid + 1; else hi = mid; }
    int end = lo;
    int cnt = end - start;

    float sc = 0.f, sh = 0.f;
    if (lane < 20) {
        sc = __ldg(&bn2_g[lane]) * rsqrtf(__ldg(&bn2_v[lane]) + BN_EPS);
        sh = __ldg(&bn2_b[lane]) - __ldg(&bn2_m[lane]) * sc;
    }

    float sum0 = 0.f, sum1 = 0.f, mx0 = -INFINITY, mx1 = -INFINITY;
    if (lane < 20) {
        int nd = start;
        for (; nd + 1 < end; nd += 2) {
            float a0 = __ldg(&g_agg2[nd * 20 + lane]);
            float a1 = __ldg(&g_agg2[(nd + 1) * 20 + lane]);
            float v0 = fmaxf(a0, 0.f) * sc + sh;
            float v1 = fmaxf(a1, 0.f) * sc + sh;
            sum0 += v0; mx0 = fmaxf(mx0, v0);
            sum1 += v1; mx1 = fmaxf(mx1, v1);
        }
        if (nd < end) {
            float a0 = __ldg(&g_agg2[nd * 20 + lane]);
            float v0 = fmaxf(a0, 0.f) * sc + sh;
            sum0 += v0; mx0 = fmaxf(mx0, v0);
        }
    }
    float sum = sum0 + sum1;
    float mx = fmaxf(mx0, mx1);
    float mean = (lane < 20) ? (sum / fmaxf((float)cnt, 1.f)) : 0.f;
    if (cnt == 0 || lane >= 20) mx = 0.f;

    float o = 0.f;
#pragma unroll
    for (int j = 0; j < 10; j++) {
        float p = 0.f;
        if (lane < 20)
            p = mx * __ldg(&W1[lane * 10 + j]) + mean * __ldg(&W1[(lane + 20) * 10 + j]);
#pragma unroll
        for (int off = 16; off > 0; off >>= 1)
            p += __shfl_xor_sync(0xffffffffu, p, off);
        float z = fmaxf(p + __ldg(&bl1[j]), 0.f);
        o += z * __ldg(&W2[j]);
    }
    o += __ldg(&bl2[0]);
    float sig = 1.f / (1.f + expf(-o));
    if (lane == 0) out[g] = sig;
}

// ---------------- launch -----------------------------------------------------
extern "C" void kernel_launch(void* const* d_in, const int* in_sizes, int n_in,
                              void* d_out, int out_size) {
    const float* x      = (const float*)d_in[0];
    const int*   ei     = (const int*)  d_in[1];
    const int*   batch  = (const int*)  d_in[2];
    const float* Wrel1  = (const float*)d_in[3];
    const float* Wroot1 = (const float*)d_in[4];
    const float* b1     = (const float*)d_in[5];
    const float* bn1_g  = (const float*)d_in[6];
    const float* bn1_b  = (const float*)d_in[7];
    const float* bn1_m  = (const float*)d_in[8];
    const float* bn1_v  = (const float*)d_in[9];
    const float* Wrel2  = (const float*)d_in[10];
    const float* Wroot2 = (const float*)d_in[11];
    const float* b2     = (const float*)d_in[12];
    const float* bn2_g  = (const float*)d_in[13];
    const float* bn2_b  = (const float*)d_in[14];
    const float* bn2_m  = (const float*)d_in[15];
    const float* bn2_v  = (const float*)d_in[16];
    const float* W1     = (const float*)d_in[17];
    const float* bl1    = (const float*)d_in[18];
    const float* W2     = (const float*)d_in[19];
    const float* bl2    = (const float*)d_in[20];
    float* out = (float*)d_out;

    int n  = in_sizes[0] / NF;   // nodes
    int nE = in_sizes[1] / 2;    // edges

    k_node1<<<(n + 255) / 256, 128>>>(x, Wrel1, Wroot1, b1, n);
    {
        long long total = (long long)nE * 4;
        k_scatter1<<<(unsigned)((total + 255) / 256), 256>>>(ei, nE);
    }
    k_node2<<<(n + 255) / 256, 128>>>(bn1_g, bn1_b, bn1_m, bn1_v,
                                      Wrel2, Wroot2, b2, n);
    {
        long long total = (long long)nE * 5;
        k_scatter2<<<(unsigned)((total + 255) / 256), 256>>>(ei, nE);
    }
    k_pool_head<<<NG, 32>>>(batch, n, bn2_g, bn2_b, bn2_m, bn2_v,
                            W1, bl1, W2, bl2, out);
}

// round 13
// speedup vs baseline: 1.4335x; 1.4335x over previous
#include <cuda_runtime.h>
#include <cuda_fp16.h>
#include <math.h>

#define NN 100000          // nodes
#define NE 3200000         // edges
#define NG 512             // graphs
#define NF 128             // input features
#define BN_EPS 1e-5f
#define STR1 (NN * 32)     // stride of one agg1 fp16 buffer

// ---------------- scratch (device globals; no allocations allowed) ----------
__device__ __half g_y1h[NN * 32];       // fp16(x @ W_rel1), padded 30->32 (64B rows)
__device__ __half g_agg1h[4 * STR1];    // 4-way split fp16 accumulators (edge e -> buf e&3)
__device__ float  g_y2[NN * 20];        // h @ W_rel2' (bn1 folded)
__device__ float  g_agg2[NN * 20];      // init = h @ W_root2' + b2'; fp32 RED adds edges

// ---------------- helpers ----------------------------------------------------
__device__ __forceinline__ void red_add_v4_f32(float* p, float4 v) {
    asm volatile("red.global.add.v4.f32 [%0], {%1, %2, %3, %4};"
                 :: "l"(__cvta_generic_to_global(p)),
                    "f"(v.x), "f"(v.y), "f"(v.z), "f"(v.w)
                 : "memory");
}

__device__ __forceinline__ void red_add_v4_f16x2(__half* p, uint4 v) {
    asm volatile("red.global.add.noftz.v4.f16x2 [%0], {%1, %2, %3, %4};"
                 :: "l"(__cvta_generic_to_global(p)),
                    "r"(v.x), "r"(v.y), "r"(v.z), "r"(v.w)
                 : "memory");
}

__device__ __forceinline__ float2 ffma2(float2 a, float2 b, float2 c) {
    float2 d;
    asm("fma.rn.f32x2 %0, %1, %2, %3;"
        : "=l"(reinterpret_cast<unsigned long long&>(d))
        : "l"(reinterpret_cast<unsigned long long&>(a)),
          "l"(reinterpret_cast<unsigned long long&>(b)),
          "l"(reinterpret_cast<unsigned long long&>(c)));
    return d;
}

// ---------------- kernel 1: node transform 1 (1 node/thread, R10 proven) ----
// g_y1h = fp16(x @ W_rel1); agg1 buf0 = fp16(x @ W_root1 + b1); bufs 1-3 = 0
__global__ void __launch_bounds__(128) k_node1(
    const float* __restrict__ x,
    const float* __restrict__ Wrel,   // [128,30]
    const float* __restrict__ Wroot,  // [128,30]
    const float* __restrict__ b1,     // [30]
    int n)
{
    __shared__ float Ws[128 * 60];    // row k: [rel 30 | root 30]
    __shared__ float bs[30];
    for (int i = threadIdx.x; i < 128 * 30; i += 128) {
        int k = i / 30, j = i % 30;
        Ws[k * 60 + j]      = Wrel[i];
        Ws[k * 60 + 30 + j] = Wroot[i];
    }
    if (threadIdx.x < 30) bs[threadIdx.x] = b1[threadIdx.x];
    __syncthreads();

    int node = blockIdx.x * 128 + threadIdx.x;
    if (node >= n) return;

    float2 acc[30];                   // pairs (2p,2p+1): 0..14 rel, 15..29 root
#pragma unroll
    for (int p = 0; p < 30; p++) acc[p] = make_float2(0.f, 0.f);

    const float4* xr = reinterpret_cast<const float4*>(x) + node * 32;
#pragma unroll 4
    for (int k4 = 0; k4 < 32; k4++) {
        float4 xv = __ldg(xr + k4);
#pragma unroll
        for (int q = 0; q < 4; q++) {
            float xs = (q == 0) ? xv.x : (q == 1) ? xv.y : (q == 2) ? xv.z : xv.w;
            float2 xb = make_float2(xs, xs);
            const float4* w4 = reinterpret_cast<const float4*>(&Ws[(k4 * 4 + q) * 60]);
#pragma unroll
            for (int j4 = 0; j4 < 15; j4++) {
                float4 wv = w4[j4];
                acc[j4 * 2]     = ffma2(make_float2(wv.x, wv.y), xb, acc[j4 * 2]);
                acc[j4 * 2 + 1] = ffma2(make_float2(wv.z, wv.w), xb, acc[j4 * 2 + 1]);
            }
        }
    }

    // y1h = fp16 rel pairs 0..14 (+1 zero pair)
    {
        __half2 h2[16];
#pragma unroll
        for (int p = 0; p < 15; p++) h2[p] = __float22half2_rn(acc[p]);
        h2[15] = __float2half2_rn(0.f);
        uint4* yo = reinterpret_cast<uint4*>(g_y1h + node * 32);
#pragma unroll
        for (int c = 0; c < 4; c++) yo[c] = reinterpret_cast<uint4*>(h2)[c];
    }
    // agg1 buf0 init = fp16(root + b1); bufs 1..3 zeroed
    {
        __half2 h2[16];
#pragma unroll
        for (int p = 0; p < 15; p++)
            h2[p] = __float22half2_rn(make_float2(acc[15 + p].x + bs[2 * p],
                                                  acc[15 + p].y + bs[2 * p + 1]));
        h2[15] = __float2half2_rn(0.f);
        uint4* ao = reinterpret_cast<uint4*>(g_agg1h + node * 32);
#pragma unroll
        for (int c = 0; c < 4; c++) ao[c] = reinterpret_cast<uint4*>(h2)[c];

        uint4 z4 = make_uint4(0u, 0u, 0u, 0u);
#pragma unroll
        for (int b = 1; b < 4; b++) {
            uint4* zo = reinterpret_cast<uint4*>(g_agg1h + (size_t)b * STR1 + node * 32);
#pragma unroll
            for (int c = 0; c < 4; c++) zo[c] = z4;
        }
    }
}

// ---------------- kernel 2: edge scatter 1 (4 chunk-lanes/edge, fp16 RED) ----
// edge e accumulates into split buffer (e & 3)
__global__ void __launch_bounds__(256) k_scatter1(const int* __restrict__ ei, int nE)
{
    long long gtid = (long long)blockIdx.x * blockDim.x + threadIdx.x;
    if (gtid >= (long long)nE * 4) return;
    int e = (int)(gtid >> 2);
    int c = (int)(gtid & 3);
    int s = __ldg(&ei[e]);
    int d = __ldg(&ei[nE + e]);
    uint4 v = __ldg(reinterpret_cast<const uint4*>(g_y1h) + s * 4 + c);
    int buf = e & 3;
    red_add_v4_f16x2(g_agg1h + (size_t)buf * STR1 + d * 32 + c * 8, v);
}

// ---------------- kernel 3: node transform 2 (1 node/thread, bn1 folded) ----
__global__ void __launch_bounds__(128) k_node2(
    const float* __restrict__ bn1_g, const float* __restrict__ bn1_b,
    const float* __restrict__ bn1_m, const float* __restrict__ bn1_v,
    const float* __restrict__ Wrel2,   // [30,20]
    const float* __restrict__ Wroot2,  // [30,20]
    const float* __restrict__ b2,      // [20]
    int n)
{
    __shared__ float Ws[30 * 40];     // row k: [rel 20 | root 20] scaled by sc1[k]
    __shared__ float sc1[30], sh1[30];
    __shared__ float cr[20], cq[20];

    if (threadIdx.x < 30) {
        float sc = bn1_g[threadIdx.x] * rsqrtf(bn1_v[threadIdx.x] + BN_EPS);
        sc1[threadIdx.x] = sc;
        sh1[threadIdx.x] = bn1_b[threadIdx.x] - bn1_m[threadIdx.x] * sc;
    }
    __syncthreads();
    for (int i = threadIdx.x; i < 30 * 20; i += 128) {
        int k = i / 20, j = i % 20;
        Ws[k * 40 + j]      = sc1[k] * Wrel2[i];
        Ws[k * 40 + 20 + j] = sc1[k] * Wroot2[i];
    }
    if (threadIdx.x < 40) {
        int j = threadIdx.x % 20;
        float s = (threadIdx.x < 20) ? 0.f : b2[j];
        if (threadIdx.x < 20) {
            for (int k = 0; k < 30; k++) s += sh1[k] * Wrel2[k * 20 + j];
            cr[j] = s;
        } else {
            for (int k = 0; k < 30; k++) s += sh1[k] * Wroot2[k * 20 + j];
            cq[j] = s;
        }
    }
    __syncthreads();

    int node = blockIdx.x * 128 + threadIdx.x;
    if (node >= n) return;

    // sum the 4 split fp16 buffers in fp32, then relu
    float h[30];
    {
        float2 accs[15];
#pragma unroll
        for (int p = 0; p < 15; p++) accs[p] = make_float2(0.f, 0.f);
#pragma unroll
        for (int b = 0; b < 4; b++) {
            const uint4* ar = reinterpret_cast<const uint4*>(g_agg1h + (size_t)b * STR1 + node * 32);
            uint4 q[4];
#pragma unroll
            for (int c = 0; c < 4; c++) q[c] = __ldg(ar + c);
            const __half2* hp = reinterpret_cast<const __half2*>(q);
#pragma unroll
            for (int p = 0; p < 15; p++) {
                float2 f = __half22float2(hp[p]);
                accs[p].x += f.x; accs[p].y += f.y;
            }
        }
#pragma unroll
        for (int p = 0; p < 15; p++) {
            h[2 * p]     = fmaxf(accs[p].x, 0.f);
            h[2 * p + 1] = fmaxf(accs[p].y, 0.f);
        }
    }

    float2 acc[20];                   // pairs (2p,2p+1): 0..9 rel, 10..19 root
#pragma unroll
    for (int p = 0; p < 10; p++) {
        acc[p]      = make_float2(cr[p*2], cr[p*2+1]);
        acc[10 + p] = make_float2(cq[p*2], cq[p*2+1]);
    }

#pragma unroll
    for (int k = 0; k < 30; k++) {
        float2 xb = make_float2(h[k], h[k]);
        const float4* w4 = reinterpret_cast<const float4*>(&Ws[k * 40]);
#pragma unroll
        for (int j4 = 0; j4 < 10; j4++) {
            float4 wv = w4[j4];
            acc[j4 * 2]     = ffma2(make_float2(wv.x, wv.y), xb, acc[j4 * 2]);
            acc[j4 * 2 + 1] = ffma2(make_float2(wv.z, wv.w), xb, acc[j4 * 2 + 1]);
        }
    }

    float4* y = reinterpret_cast<float4*>(g_y2 + node * 20);
#pragma unroll
    for (int j4 = 0; j4 < 5; j4++)
        y[j4] = make_float4(acc[j4*2].x, acc[j4*2].y, acc[j4*2+1].x, acc[j4*2+1].y);

    float4* a = reinterpret_cast<float4*>(g_agg2 + node * 20);
#pragma unroll
    for (int j4 = 0; j4 < 5; j4++) {
        float2 p0 = acc[10 + j4*2], p1 = acc[11 + j4*2];
        a[j4] = make_float4(p0.x, p0.y, p1.x, p1.y);
    }
}

// ---------------- kernel 4: edge scatter 2 (5 chunk-lanes/edge, fp32 RED) ----
__global__ void __launch_bounds__(256) k_scatter2(const int* __restrict__ ei, int nE)
{
    long long gtid = (long long)blockIdx.x * blockDim.x + threadIdx.x;
    if (gtid >= (long long)nE * 5) return;
    unsigned int u = (unsigned int)gtid;
    unsigned int e = u / 5u;
    unsigned int c = u - e * 5u;
    int s = __ldg(&ei[e]);
    int d = __ldg(&ei[nE + e]);
    float4 v = __ldg(reinterpret_cast<const float4*>(g_y2) + s * 5 + c);
    red_add_v4_f32(g_agg2 + d * 20 + c * 4, v);
}

// ---------------- kernel 5: per-graph pooling + MLP head ---------------------
__global__ void __launch_bounds__(32) k_pool_head(
    const int* __restrict__ batch, int n,
    const float* __restrict__ bn2_g, const float* __restrict__ bn2_b,
    const float* __restrict__ bn2_m, const float* __restrict__ bn2_v,
    const float* __restrict__ W1,    // [40,10]
    const float* __restrict__ bl1,   // [10]
    const float* __restrict__ W2,    // [10,1]
    const float* __restrict__ bl2,   // [1]
    float* __restrict__ out)
{
    int g = blockIdx.x;
    int lane = threadIdx.x;

    int lo = 0, hi = n;
    while (lo < hi) { int mid = (lo + hi) >> 1; if (__ldg(&batch[mid]) < g) lo = mid + 1; else hi = mid; }
    int start = lo;
    lo = start; hi = n;
    while (lo < hi) { int mid = (lo + hi) >> 1; if (__ldg(&batch[mid]) < g + 1) lo = mid + 1; else hi = mid; }
    int end = lo;
    int cnt = end - start;

    float sc = 0.f, sh = 0.f;
    if (lane < 20) {
        sc = __ldg(&bn2_g[lane]) * rsqrtf(__ldg(&bn2_v[lane]) + BN_EPS);
        sh = __ldg(&bn2_b[lane]) - __ldg(&bn2_m[lane]) * sc;
    }

    float sum0 = 0.f, sum1 = 0.f, mx0 = -INFINITY, mx1 = -INFINITY;
    if (lane < 20) {
        int nd = start;
        for (; nd + 1 < end; nd += 2) {
            float a0 = __ldg(&g_agg2[nd * 20 + lane]);
            float a1 = __ldg(&g_agg2[(nd + 1) * 20 + lane]);
            float v0 = fmaxf(a0, 0.f) * sc + sh;
            float v1 = fmaxf(a1, 0.f) * sc + sh;
            sum0 += v0; mx0 = fmaxf(mx0, v0);
            sum1 += v1; mx1 = fmaxf(mx1, v1);
        }
        if (nd < end) {
            float a0 = __ldg(&g_agg2[nd * 20 + lane]);
            float v0 = fmaxf(a0, 0.f) * sc + sh;
            sum0 += v0; mx0 = fmaxf(mx0, v0);
        }
    }
    float sum = sum0 + sum1;
    float mx = fmaxf(mx0, mx1);
    float mean = (lane < 20) ? (sum / fmaxf((float)cnt, 1.f)) : 0.f;
    if (cnt == 0 || lane >= 20) mx = 0.f;

    float o = 0.f;
#pragma unroll
    for (int j = 0; j < 10; j++) {
        float p = 0.f;
        if (lane < 20)
            p = mx * __ldg(&W1[lane * 10 + j]) + mean * __ldg(&W1[(lane + 20) * 10 + j]);
#pragma unroll
        for (int off = 16; off > 0; off >>= 1)
            p += __shfl_xor_sync(0xffffffffu, p, off);
        float z = fmaxf(p + __ldg(&bl1[j]), 0.f);
        o += z * __ldg(&W2[j]);
    }
    o += __ldg(&bl2[0]);
    float sig = 1.f / (1.f + expf(-o));
    if (lane == 0) out[g] = sig;
}

// ---------------- launch -----------------------------------------------------
extern "C" void kernel_launch(void* const* d_in, const int* in_sizes, int n_in,
                              void* d_out, int out_size) {
    const float* x      = (const float*)d_in[0];
    const int*   ei     = (const int*)  d_in[1];
    const int*   batch  = (const int*)  d_in[2];
    const float* Wrel1  = (const float*)d_in[3];
    const float* Wroot1 = (const float*)d_in[4];
    const float* b1     = (const float*)d_in[5];
    const float* bn1_g  = (const float*)d_in[6];
    const float* bn1_b  = (const float*)d_in[7];
    const float* bn1_m  = (const float*)d_in[8];
    const float* bn1_v  = (const float*)d_in[9];
    const float* Wrel2  = (const float*)d_in[10];
    const float* Wroot2 = (const float*)d_in[11];
    const float* b2     = (const float*)d_in[12];
    const float* bn2_g  = (const float*)d_in[13];
    const float* bn2_b  = (const float*)d_in[14];
    const float* bn2_m  = (const float*)d_in[15];
    const float* bn2_v  = (const float*)d_in[16];
    const float* W1     = (const float*)d_in[17];
    const float* bl1    = (const float*)d_in[18];
    const float* W2     = (const float*)d_in[19];
    const float* bl2    = (const float*)d_in[20];
    float* out = (float*)d_out;

    int n  = in_sizes[0] / NF;   // nodes
    int nE = in_sizes[1] / 2;    // edges

    k_node1<<<(n + 127) / 128, 128>>>(x, Wrel1, Wroot1, b1, n);
    {
        long long total = (long long)nE * 4;
        k_scatter1<<<(unsigned)((total + 255) / 256), 256>>>(ei, nE);
    }
    k_node2<<<(n + 127) / 128, 128>>>(bn1_g, bn1_b, bn1_m, bn1_v,
                                      Wrel2, Wroot2, b2, n);
    {
        long long total = (long long)nE * 5;
        k_scatter2<<<(unsigned)((total + 255) / 256), 256>>>(ei, nE);
    }
    k_pool_head<<<NG, 32>>>(batch, n, bn2_g, bn2_b, bn2_m, bn2_v,
                            W1, bl1, W2, bl2, out);
}